// round 2
// baseline (speedup 1.0000x reference)
#include <cuda_runtime.h>
#include <math.h>

#define SEQ 2048
#define BATCH 64
#define M_ROWS (SEQ*BATCH)   // 131072

// ---------------- scratch (device globals; no allocation allowed) -------------
__device__ float g_act0[M_ROWS*256];          // 134 MB ping
__device__ float g_act1[M_ROWS*256];          // 134 MB pong
__device__ float g_xw[2*M_ROWS*512];          // 536 MB: [dir][row][4H] (max layer)
__device__ float g_part[256*512];             // bn partials: [blk][2C]
__device__ float g_scale[256];
__device__ float g_shift[256];

// ---------------- activations ------------------------------------------------
__device__ __forceinline__ float sigm(float x) {
    return 1.f / (1.f + __expf(-x));
}
__device__ __forceinline__ float tanh_(float x) {
    float e = __expf(-2.f * fabsf(x));
    float t = (1.f - e) / (1.f + e);
    return copysignf(t, x);
}

// ---------------- xW GEMM -----------------------------------------------------
// out xw[d][r][gate] = sum_k in(t(r),b(r),k) * Wih[d][gate][k] + bih+bhh
// layer>0 input has BN affine applied on load. dir 1 reads time-reversed input.
template<int IC, int NG, bool FIRST>
__global__ __launch_bounds__(256)
void gemm_xw(const float* __restrict__ xin,
             const float* __restrict__ wih,
             const float* __restrict__ bihp,
             const float* __restrict__ bhhp,
             const float* __restrict__ scale,
             const float* __restrict__ shift,
             float* __restrict__ xw)
{
    constexpr int TM = 128, TN = 64, KC = 16;
    const int d      = blockIdx.z;
    const int r0     = blockIdx.x * TM;
    const int n0blk  = blockIdx.y * TN;
    __shared__ float Xs[KC][TM];
    __shared__ float Ws[KC][TN + 4];

    float acc[8][4];
#pragma unroll
    for (int i = 0; i < 8; i++)
#pragma unroll
        for (int j = 0; j < 4; j++) acc[i][j] = 0.f;

    const int tx = threadIdx.x & 15;          // n dim: 16 * 4 = 64
    const int ty = threadIdx.x >> 4;          // m dim: 16 * 8 = 128
    const int mreg = ty * 8, nreg = tx * 4;

    constexpr int NCHUNK = (IC + KC - 1) / KC;
#pragma unroll 1
    for (int kc = 0; kc < NCHUNK; kc++) {
        const int k0 = kc * KC;
        // ---- load X tile (with affine / layer-0 layout / time reversal) ----
        {
            int m  = threadIdx.x & 127;
            int ks = (threadIdx.x >> 7) * 8;
            int r  = r0 + m;
            int t  = r >> 6;                  // / BATCH
            int b  = r & 63;
            int tt = d ? (SEQ - 1 - t) : t;
#pragma unroll
            for (int j = 0; j < 8; j++) {
                int k = ks + j;
                float v = 0.f;
                if (k0 + k < IC) {
                    if (FIRST) {
                        v = xin[(size_t)b * SEQ * 7 + (size_t)tt * 7 + (k0 + k)];
                    } else {
                        float a = xin[((size_t)tt * BATCH + b) * IC + (k0 + k)];
                        v = fmaf(a, scale[k0 + k], shift[k0 + k]);
                    }
                }
                Xs[k][m] = v;
            }
        }
        // ---- load W tile ----
        {
            int n  = threadIdx.x & 63;
            int kg = (threadIdx.x >> 6) * 4;
#pragma unroll
            for (int j = 0; j < 4; j++) {
                int k = kg + j;
                float v = 0.f;
                if (k0 + k < IC)
                    v = wih[((size_t)d * NG + n0blk + n) * IC + (k0 + k)];
                Ws[k][n] = v;
            }
        }
        __syncthreads();
        // ---- compute ----
#pragma unroll
        for (int k = 0; k < KC; k++) {
            float4 x0 = *(const float4*)&Xs[k][mreg];
            float4 x1 = *(const float4*)&Xs[k][mreg + 4];
            float4 w0 = *(const float4*)&Ws[k][nreg];
            float xr[8] = {x0.x, x0.y, x0.z, x0.w, x1.x, x1.y, x1.z, x1.w};
            float wr[4] = {w0.x, w0.y, w0.z, w0.w};
#pragma unroll
            for (int i = 0; i < 8; i++)
#pragma unroll
                for (int j = 0; j < 4; j++)
                    acc[i][j] = fmaf(xr[i], wr[j], acc[i][j]);
        }
        __syncthreads();
    }
    // ---- epilogue: + (bih+bhh), store ----
    float bs[4];
#pragma unroll
    for (int j = 0; j < 4; j++) {
        int g = n0blk + nreg + j;
        bs[j] = bihp[d * NG + g] + bhhp[d * NG + g];
    }
#pragma unroll
    for (int i = 0; i < 8; i++) {
        int r = r0 + mreg + i;
        float4 o;
        o.x = acc[i][0] + bs[0];
        o.y = acc[i][1] + bs[1];
        o.z = acc[i][2] + bs[2];
        o.w = acc[i][3] + bs[3];
        *(float4*)&xw[((size_t)d * M_ROWS + r) * NG + n0blk + nreg] = o;
    }
}

// ---------------- recurrent LSTM kernel --------------------------------------
// One CTA = (dir, BT batch rows). Thread owns one gate row of Whh in registers
// (for H=128, half in registers + half in padded smem). c state lives in the
// registers of the first H threads of each row.
template<int H, int BT, bool HYB>
__global__ __launch_bounds__(512)
void lstm_rec(const float* __restrict__ whh,   // [2][4H][H]
              const float* __restrict__ xw,    // [2][M][4H] (dir1 pre-reversed)
              float* __restrict__ out)         // [S][B][2H]
{
    constexpr int NG   = 4 * H;
    constexpr int KREG = HYB ? 64 : H;
    constexpr int KS   = H - KREG;
    constexpr int W2ROW = HYB ? (KS + 4) : 1;  // floats per gate row in smem

    extern __shared__ float sm[];
    float* h_sh = sm;                 // BT*H
    float* gbuf = sm + BT * H;        // BT*NG
    float* w2   = gbuf + BT * NG;     // HYB only

    const int tid  = threadIdx.x;
    const int row  = tid / NG;
    const int gate = tid % NG;
    const int d    = blockIdx.y;
    const int b0   = blockIdx.x * BT;

    // register weights
    float4 wr[KREG / 4];
    {
        const float4* wsrc = (const float4*)(whh + ((size_t)d * NG + gate) * H);
#pragma unroll
        for (int i = 0; i < KREG / 4; i++) wr[i] = wsrc[i];
    }
    if (HYB) {
        for (int e = tid; e < NG * KS; e += blockDim.x) {
            int g = e / KS, kk = e % KS;
            w2[g * W2ROW + kk] = whh[((size_t)d * NG + g) * H + KREG + kk];
        }
    }
    for (int i = tid; i < BT * H; i += blockDim.x) h_sh[i] = 0.f;
    __syncthreads();

    float c = 0.f;
    const float* xwp = xw + (size_t)d * M_ROWS * NG + (size_t)(b0 + row) * NG + gate;
    const size_t xstep = (size_t)BATCH * NG;
    float nxt = xwp[0];

#pragma unroll 1
    for (int t = 0; t < SEQ; t++) {
        float acc = nxt;
        if (t + 1 < SEQ) nxt = xwp[(size_t)(t + 1) * xstep];   // prefetch

        const float4* hb = (const float4*)(h_sh + row * H);
#pragma unroll
        for (int k4 = 0; k4 < KREG / 4; k4++) {
            float4 hv = hb[k4];
            acc = fmaf(wr[k4].x, hv.x, acc);
            acc = fmaf(wr[k4].y, hv.y, acc);
            acc = fmaf(wr[k4].z, hv.z, acc);
            acc = fmaf(wr[k4].w, hv.w, acc);
        }
        if (HYB) {
            const float4* wg = (const float4*)(w2 + gate * W2ROW);
#pragma unroll
            for (int k4 = 0; k4 < KS / 4; k4++) {
                float4 hv = hb[KREG / 4 + k4];
                float4 wv = wg[k4];
                acc = fmaf(wv.x, hv.x, acc);
                acc = fmaf(wv.y, hv.y, acc);
                acc = fmaf(wv.z, hv.z, acc);
                acc = fmaf(wv.w, hv.w, acc);
            }
        }
        gbuf[row * NG + gate] = acc;
        __syncthreads();

        if (gate < H) {
            const int u = gate;
            float gi = sigm (gbuf[row * NG + u]);
            float gf = sigm (gbuf[row * NG + H + u]);
            float gg = tanh_(gbuf[row * NG + 2 * H + u]);
            float go = sigm (gbuf[row * NG + 3 * H + u]);
            c = fmaf(gf, c, gi * gg);
            float h = go * tanh_(c);
            h_sh[row * H + u] = h;
            int s = d ? (SEQ - 1 - t) : t;
            out[((size_t)s * BATCH + (b0 + row)) * (2 * H) + d * H + u] = h;
        }
        __syncthreads();
    }
}

// ---------------- BN stats (deterministic two-pass) ---------------------------
template<int C>
__global__ __launch_bounds__(256)
void bn_stats(const float* __restrict__ act, float* __restrict__ part)
{
    // flat length M_ROWS*C; chunk per block is a multiple of 256 and of C,
    // so each thread's elements all belong to channel (tid % C).
    const long chunk = (long)(M_ROWS / 256) * C;          // 512*C
    long base = (long)blockIdx.x * chunk;
    float s = 0.f, q = 0.f;
    for (long e = base + threadIdx.x; e < base + chunk; e += 256) {
        float v = act[e];
        s += v;
        q = fmaf(v, v, q);
    }
    __shared__ float red[512];
    red[threadIdx.x] = s;
    red[256 + threadIdx.x] = q;
    __syncthreads();
    int c = threadIdx.x;
    if (c < C) {
        float ss = 0.f, qq = 0.f;
#pragma unroll 1
        for (int j = 0; j < 256 / C; j++) {
            ss += red[c + j * C];
            qq += red[256 + c + j * C];
        }
        part[blockIdx.x * 2 * C + c]     = ss;
        part[blockIdx.x * 2 * C + C + c] = qq;
    }
}

__global__ void bn_finalize(const float* __restrict__ part,
                            const float* __restrict__ gamma,
                            const float* __restrict__ beta,
                            float* __restrict__ scale,
                            float* __restrict__ shift, int C)
{
    int c = threadIdx.x;
    if (c >= C) return;
    float s = 0.f, q = 0.f;
    for (int b = 0; b < 256; b++) {
        s += part[b * 2 * C + c];
        q += part[b * 2 * C + C + c];
    }
    float inv  = 1.f / (float)M_ROWS;
    float mean = s * inv;
    float var  = q * inv - mean * mean;
    float sc   = gamma[c] * rsqrtf(var + 1e-5f);
    scale[c] = sc;
    shift[c] = beta[c] - mean * sc;
}

// ---------------- final FC (BN affine folded into row load) -------------------
__global__ __launch_bounds__(256)
void fc_kernel(const float* __restrict__ act,     // [S][B][256]
               const float* __restrict__ scale,
               const float* __restrict__ shift,
               const float* __restrict__ fcw,     // [11][256]
               const float* __restrict__ fcb,     // [11]
               float* __restrict__ out)           // [B][S][11]
{
    __shared__ float rows[16][256];
    __shared__ float wsm[11][256];
    const int tid = threadIdx.x;
    for (int e = tid; e < 11 * 256; e += 256) wsm[e / 256][e % 256] = fcw[e];
    const int r0 = blockIdx.x * 16;
#pragma unroll
    for (int i = 0; i < 16; i++) {
        float v = act[((size_t)(r0 + i)) * 256 + tid];
        rows[i][tid] = fmaf(v, scale[tid], shift[tid]);
    }
    __syncthreads();
    if (tid < 176) {
        int i = tid / 11, o = tid % 11;
        const float4* rp = (const float4*)rows[i];
        const float4* wp = (const float4*)wsm[o];
        float a = 0.f;
#pragma unroll
        for (int k = 0; k < 64; k++) {
            float4 rv = rp[k], wv = wp[k];
            a = fmaf(rv.x, wv.x, a);
            a = fmaf(rv.y, wv.y, a);
            a = fmaf(rv.z, wv.z, a);
            a = fmaf(rv.w, wv.w, a);
        }
        a += fcb[o];
        int r = r0 + i;
        int b = r & 63, t = r >> 6;
        out[((size_t)b * SEQ + t) * 11 + o] = a;
    }
}

// ---------------- host orchestration -----------------------------------------
extern "C" void kernel_launch(void* const* d_in, const int* in_sizes, int n_in,
                              void* d_out, int out_size)
{
    (void)in_sizes; (void)n_in; (void)out_size;
    // metadata order = setup_inputs() dict insertion order:
    //   0: x
    //   per layer l (stride 6, base 1+6l): wih, whh, bih, bhh, gamma, beta
    //   25: fc_w   26: fc_b
    const float* x = (const float*)d_in[0];
    const float *wih[4], *whh[4], *bih[4], *bhh[4], *gamma[4], *beta[4];
    for (int l = 0; l < 4; l++) {
        wih[l]   = (const float*)d_in[1 + 6 * l];
        whh[l]   = (const float*)d_in[2 + 6 * l];
        bih[l]   = (const float*)d_in[3 + 6 * l];
        bhh[l]   = (const float*)d_in[4 + 6 * l];
        gamma[l] = (const float*)d_in[5 + 6 * l];
        beta[l]  = (const float*)d_in[6 + 6 * l];
    }
    const float* fcw = (const float*)d_in[25];
    const float* fcb = (const float*)d_in[26];
    float* out = (float*)d_out;

    float *act0, *act1, *xw, *part, *scl, *shf;
    cudaGetSymbolAddress((void**)&act0, g_act0);
    cudaGetSymbolAddress((void**)&act1, g_act1);
    cudaGetSymbolAddress((void**)&xw,   g_xw);
    cudaGetSymbolAddress((void**)&part, g_part);
    cudaGetSymbolAddress((void**)&scl,  g_scale);
    cudaGetSymbolAddress((void**)&shf,  g_shift);

    const int sm_small = (128 + 512) * 4;                 // 2560 B
    const int sm_big   = (128 + 512 + 512 * 68) * 4;      // 141824 B
    cudaFuncSetAttribute(lstm_rec<128, 1, true>,
                         cudaFuncAttributeMaxDynamicSharedMemorySize, sm_big);

    // ---- layer 0: I=7, H=16 ----
    gemm_xw<7, 64, true><<<dim3(1024, 1, 2), 256>>>(x, wih[0], bih[0], bhh[0],
                                                    nullptr, nullptr, xw);
    lstm_rec<16, 8, false><<<dim3(8, 2), 512, sm_small>>>(whh[0], xw, act0);
    bn_stats<32><<<256, 256>>>(act0, part);
    bn_finalize<<<1, 32>>>(part, gamma[0], beta[0], scl, shf, 32);

    // ---- layer 1: I=32, H=32 ----
    gemm_xw<32, 128, false><<<dim3(1024, 2, 2), 256>>>(act0, wih[1], bih[1], bhh[1],
                                                       scl, shf, xw);
    lstm_rec<32, 4, false><<<dim3(16, 2), 512, sm_small>>>(whh[1], xw, act1);
    bn_stats<64><<<256, 256>>>(act1, part);
    bn_finalize<<<1, 64>>>(part, gamma[1], beta[1], scl, shf, 64);

    // ---- layer 2: I=64, H=64 ----
    gemm_xw<64, 256, false><<<dim3(1024, 4, 2), 256>>>(act1, wih[2], bih[2], bhh[2],
                                                       scl, shf, xw);
    lstm_rec<64, 2, false><<<dim3(32, 2), 512, sm_small>>>(whh[2], xw, act0);
    bn_stats<128><<<256, 256>>>(act0, part);
    bn_finalize<<<1, 128>>>(part, gamma[2], beta[2], scl, shf, 128);

    // ---- layer 3: I=128, H=128 ----
    gemm_xw<128, 512, false><<<dim3(1024, 8, 2), 256>>>(act0, wih[3], bih[3], bhh[3],
                                                        scl, shf, xw);
    lstm_rec<128, 1, true><<<dim3(64, 2), 512, sm_big>>>(whh[3], xw, act1);
    bn_stats<256><<<256, 256>>>(act1, part);
    bn_finalize<<<1, 256>>>(part, gamma[3], beta[3], scl, shf, 256);

    // ---- FC ----
    fc_kernel<<<8192, 256>>>(act1, scl, shf, fcw, fcb, out);
}

// round 3
// speedup vs baseline: 1.2163x; 1.2163x over previous
#include <cuda_runtime.h>
#include <math.h>

#define SEQ 2048
#define BATCH 64
#define M_ROWS (SEQ*BATCH)   // 131072

typedef unsigned long long u64;

// ---------------- scratch (device globals; no allocation allowed) -------------
__device__ float g_act0[M_ROWS*256];
__device__ float g_act1[M_ROWS*256];
__device__ float g_xw[2*M_ROWS*512];
__device__ float g_part[256*512];
__device__ float g_scale[256];
__device__ float g_shift[256];

// ---------------- f32x2 helpers ----------------------------------------------
__device__ __forceinline__ u64 pk(float lo, float hi) {
    u64 r; asm("mov.b64 %0,{%1,%2};" : "=l"(r) : "f"(lo), "f"(hi)); return r;
}
__device__ __forceinline__ u64 dup(float v) {
    u64 r; asm("mov.b64 %0,{%1,%1};" : "=l"(r) : "f"(v)); return r;
}
__device__ __forceinline__ void fma2(u64& d, u64 a, u64 b) {
    asm("fma.rn.f32x2 %0,%1,%2,%0;" : "+l"(d) : "l"(a), "l"(b));
}
__device__ __forceinline__ float2 upk(u64 v) {
    float2 r; asm("mov.b64 {%0,%1},%2;" : "=f"(r.x), "=f"(r.y) : "l"(v)); return r;
}

// ---------------- activations ------------------------------------------------
__device__ __forceinline__ float sigm(float x) {
    return 1.f / (1.f + __expf(-x));
}
__device__ __forceinline__ float tanh_(float x) {
    float e = __expf(-2.f * fabsf(x));
    float t = (1.f - e) / (1.f + e);
    return copysignf(t, x);
}

// ---------------- xW GEMM (f32x2, TM=128, TN=64/128) --------------------------
// xw[d][r][gate] = sum_k in(t(r),b(r),k)*Wih[d][gate][k] + bih+bhh
template<int IC, int NG, int TN, bool FIRST>
__global__ __launch_bounds__(256)
void gemm_xw(const float* __restrict__ xin,
             const float* __restrict__ wih,
             const float* __restrict__ bihp,
             const float* __restrict__ bhhp,
             const float* __restrict__ scale,
             const float* __restrict__ shift,
             float* __restrict__ xw)
{
    constexpr int TM = 128, KC = 16;
    constexpr int NJ = TN / 16;             // cols per thread (4 or 8)
    const int d     = blockIdx.z;
    const int r0    = blockIdx.x * TM;
    const int n0blk = blockIdx.y * TN;
    __shared__ float Xs[KC][TM];
    __shared__ float Ws[KC][TN + 4];

    u64 acc2[4][NJ];
#pragma unroll
    for (int i = 0; i < 4; i++)
#pragma unroll
        for (int j = 0; j < NJ; j++) acc2[i][j] = 0ull;

    const int tx = threadIdx.x & 15;
    const int ty = threadIdx.x >> 4;
    const int mreg = ty * 8, nreg = tx * NJ;

    constexpr int NCHUNK = (IC + KC - 1) / KC;
#pragma unroll 1
    for (int kc = 0; kc < NCHUNK; kc++) {
        const int k0 = kc * KC;
        // ---- X tile (affine folded; dir1 time-reversed) ----
        {
            int m  = threadIdx.x & 127;
            int ks = (threadIdx.x >> 7) * 8;
            int r  = r0 + m;
            int t  = r >> 6;
            int b  = r & 63;
            int tt = d ? (SEQ - 1 - t) : t;
#pragma unroll
            for (int j = 0; j < 8; j++) {
                int k = ks + j;
                float v = 0.f;
                if (k0 + k < IC) {
                    if (FIRST) {
                        v = xin[(size_t)b * SEQ * 7 + (size_t)tt * 7 + (k0 + k)];
                    } else {
                        float a = xin[((size_t)tt * BATCH + b) * IC + (k0 + k)];
                        v = fmaf(a, scale[k0 + k], shift[k0 + k]);
                    }
                }
                Xs[k][m] = v;
            }
        }
        // ---- W tile ----
        {
            constexpr int KPER = KC * TN / 256;     // 8 for TN=128, 4 for TN=64
            int n  = threadIdx.x & (TN - 1);
            int kg = (threadIdx.x / TN) * KPER;
#pragma unroll
            for (int j = 0; j < KPER; j++) {
                int k = kg + j;
                float v = 0.f;
                if (k0 + k < IC)
                    v = wih[((size_t)d * NG + n0blk + n) * IC + (k0 + k)];
                Ws[k][n] = v;
            }
        }
        __syncthreads();
        // ---- compute: pair along M, dup W ----
#pragma unroll
        for (int k = 0; k < KC; k++) {
            const ulonglong2* xa = (const ulonglong2*)&Xs[k][mreg];
            ulonglong2 xA = xa[0], xB = xa[1];
            u64 xp[4] = {xA.x, xA.y, xB.x, xB.y};
            u64 wd[NJ];
            {
                float4 w0 = *(const float4*)&Ws[k][nreg];
                wd[0] = dup(w0.x); wd[1] = dup(w0.y);
                wd[2] = dup(w0.z); wd[3] = dup(w0.w);
                if (NJ == 8) {
                    float4 w1 = *(const float4*)&Ws[k][nreg + 4];
                    wd[4] = dup(w1.x); wd[5] = dup(w1.y);
                    wd[6] = dup(w1.z); wd[7] = dup(w1.w);
                }
            }
#pragma unroll
            for (int ip = 0; ip < 4; ip++)
#pragma unroll
                for (int j = 0; j < NJ; j++)
                    fma2(acc2[ip][j], xp[ip], wd[j]);
        }
        __syncthreads();
    }
    // ---- epilogue ----
    float bs[NJ];
#pragma unroll
    for (int j = 0; j < NJ; j++) {
        int g = n0blk + nreg + j;
        bs[j] = bihp[d * NG + g] + bhhp[d * NG + g];
    }
#pragma unroll
    for (int ip = 0; ip < 4; ip++) {
        float lo[NJ], hi[NJ];
#pragma unroll
        for (int j = 0; j < NJ; j++) {
            float2 v = upk(acc2[ip][j]);
            lo[j] = v.x + bs[j];
            hi[j] = v.y + bs[j];
        }
        int r_e = r0 + mreg + 2 * ip;
        float* oe = &xw[((size_t)d * M_ROWS + r_e) * NG + n0blk + nreg];
        float* oo = oe + NG;
#pragma unroll
        for (int j4 = 0; j4 < NJ / 4; j4++) {
            *(float4*)(oe + 4 * j4) = make_float4(lo[4*j4], lo[4*j4+1], lo[4*j4+2], lo[4*j4+3]);
            *(float4*)(oo + 4 * j4) = make_float4(hi[4*j4], hi[4*j4+1], hi[4*j4+2], hi[4*j4+3]);
        }
    }
}

// ---------------- recurrent LSTM (BT=1, f32x2, reg+smem weights) --------------
// One CTA per (dir, batch). thread = gate row. KREG weights in regs, rest smem.
template<int H, int KREG>
__global__ __launch_bounds__(4*H)
void lstm_rec2(const float* __restrict__ whh,   // [2][4H][H]
               const float* __restrict__ xw,    // [2][M][4H] (dir1 pre-reversed)
               float* __restrict__ out)         // [S][B][2H]
{
    constexpr int NG = 4 * H;
    constexpr int KS = H - KREG;
    constexpr int W2ROW = 36;                    // KS<=32, pad to 36

    extern __shared__ float sm[];
    float* h_sh = sm;          // H
    float* gbuf = sm + H;      // NG
    float* w2   = gbuf + NG;   // NG*W2ROW if KS>0

    const int gate = threadIdx.x;
    const int d    = blockIdx.y;
    const int b    = blockIdx.x;

    u64 wr2[KREG / 2];
    {
        const ulonglong2* ws2 = (const ulonglong2*)(whh + ((size_t)d * NG + gate) * H);
#pragma unroll
        for (int i = 0; i < KREG / 4; i++) {
            ulonglong2 t = ws2[i];
            wr2[2 * i] = t.x; wr2[2 * i + 1] = t.y;
        }
    }
    if (KS > 0) {
        for (int e = gate; e < NG * KS; e += NG) {
            int g = e / KS, kk = e - g * KS;
            w2[g * W2ROW + kk] = whh[((size_t)d * NG + g) * H + KREG + kk];
        }
    }
    for (int i = gate; i < H; i += NG) h_sh[i] = 0.f;
    __syncthreads();

    float c = 0.f;
    const float* xwp = xw + (size_t)d * M_ROWS * NG + (size_t)b * NG + gate;
    const size_t xstep = (size_t)BATCH * NG;
    float nxt = xwp[0];

#pragma unroll 1
    for (int t = 0; t < SEQ; t++) {
        u64 a0 = pk(nxt, 0.f);
        u64 a1 = 0ull;
        if (t + 1 < SEQ) nxt = xwp[(size_t)(t + 1) * xstep];

        const ulonglong2* hb = (const ulonglong2*)h_sh;
#pragma unroll
        for (int k = 0; k < KREG / 4; k++) {
            ulonglong2 hv = hb[k];
            fma2(a0, wr2[2 * k], hv.x);
            fma2(a1, wr2[2 * k + 1], hv.y);
        }
        if (KS > 0) {
            const u64* wg = (const u64*)(w2 + gate * W2ROW);
            const u64* hg = (const u64*)(h_sh + KREG);
#pragma unroll
            for (int k = 0; k < KS / 2; k++) {
                if (k & 1) fma2(a1, wg[k], hg[k]);
                else       fma2(a0, wg[k], hg[k]);
            }
        }
        float2 pa = upk(a0), pb = upk(a1);
        gbuf[gate] = (pa.x + pa.y) + (pb.x + pb.y);
        __syncthreads();

        if (gate < H) {
            float gi = sigm (gbuf[gate]);
            float gf = sigm (gbuf[H + gate]);
            float gg = tanh_(gbuf[2 * H + gate]);
            float go = sigm (gbuf[3 * H + gate]);
            c = fmaf(gf, c, gi * gg);
            float h = go * tanh_(c);
            h_sh[gate] = h;
            int s = d ? (SEQ - 1 - t) : t;
            out[((size_t)s * BATCH + b) * (2 * H) + d * H + gate] = h;
        }
        __syncthreads();
    }
}

// ---------------- BN stats (deterministic two-pass) ---------------------------
template<int C>
__global__ __launch_bounds__(256)
void bn_stats(const float* __restrict__ act, float* __restrict__ part)
{
    const long chunk = (long)(M_ROWS / 256) * C;
    long base = (long)blockIdx.x * chunk;
    float s = 0.f, q = 0.f;
    for (long e = base + threadIdx.x; e < base + chunk; e += 256) {
        float v = act[e];
        s += v;
        q = fmaf(v, v, q);
    }
    __shared__ float red[512];
    red[threadIdx.x] = s;
    red[256 + threadIdx.x] = q;
    __syncthreads();
    int c = threadIdx.x;
    if (c < C) {
        float ss = 0.f, qq = 0.f;
#pragma unroll 1
        for (int j = 0; j < 256 / C; j++) {
            ss += red[c + j * C];
            qq += red[256 + c + j * C];
        }
        part[blockIdx.x * 2 * C + c]     = ss;
        part[blockIdx.x * 2 * C + C + c] = qq;
    }
}

__global__ void bn_finalize(const float* __restrict__ part,
                            const float* __restrict__ gamma,
                            const float* __restrict__ beta,
                            float* __restrict__ scale,
                            float* __restrict__ shift, int C)
{
    int c = threadIdx.x;
    if (c >= C) return;
    float s = 0.f, q = 0.f;
    for (int b = 0; b < 256; b++) {
        s += part[b * 2 * C + c];
        q += part[b * 2 * C + C + c];
    }
    float inv  = 1.f / (float)M_ROWS;
    float mean = s * inv;
    float var  = q * inv - mean * mean;
    float sc   = gamma[c] * rsqrtf(var + 1e-5f);
    scale[c] = sc;
    shift[c] = beta[c] - mean * sc;
}

// ---------------- final FC (BN affine folded) ---------------------------------
__global__ __launch_bounds__(256)
void fc_kernel(const float* __restrict__ act,     // [S][B][256]
               const float* __restrict__ scale,
               const float* __restrict__ shift,
               const float* __restrict__ fcw,     // [11][256]
               const float* __restrict__ fcb,     // [11]
               float* __restrict__ out)           // [B][S][11]
{
    __shared__ float rows[16][256];
    __shared__ float wsm[11][256];
    const int tid = threadIdx.x;
    for (int e = tid; e < 11 * 256; e += 256) wsm[e / 256][e % 256] = fcw[e];
    const int r0 = blockIdx.x * 16;
#pragma unroll
    for (int i = 0; i < 16; i++) {
        float v = act[((size_t)(r0 + i)) * 256 + tid];
        rows[i][tid] = fmaf(v, scale[tid], shift[tid]);
    }
    __syncthreads();
    if (tid < 176) {
        int i = tid / 11, o = tid % 11;
        const float4* rp = (const float4*)rows[i];
        const float4* wp = (const float4*)wsm[o];
        float a = 0.f;
#pragma unroll
        for (int k = 0; k < 64; k++) {
            float4 rv = rp[k], wv = wp[k];
            a = fmaf(rv.x, wv.x, a);
            a = fmaf(rv.y, wv.y, a);
            a = fmaf(rv.z, wv.z, a);
            a = fmaf(rv.w, wv.w, a);
        }
        a += fcb[o];
        int r = r0 + i;
        int b = r & 63, t = r >> 6;
        out[((size_t)b * SEQ + t) * 11 + o] = a;
    }
}

// ---------------- host orchestration -----------------------------------------
extern "C" void kernel_launch(void* const* d_in, const int* in_sizes, int n_in,
                              void* d_out, int out_size)
{
    (void)in_sizes; (void)n_in; (void)out_size;
    // metadata order: x, then per layer (stride 6): wih, whh, bih, bhh, gamma, beta
    const float* x = (const float*)d_in[0];
    const float *wih[4], *whh[4], *bih[4], *bhh[4], *gamma[4], *beta[4];
    for (int l = 0; l < 4; l++) {
        wih[l]   = (const float*)d_in[1 + 6 * l];
        whh[l]   = (const float*)d_in[2 + 6 * l];
        bih[l]   = (const float*)d_in[3 + 6 * l];
        bhh[l]   = (const float*)d_in[4 + 6 * l];
        gamma[l] = (const float*)d_in[5 + 6 * l];
        beta[l]  = (const float*)d_in[6 + 6 * l];
    }
    const float* fcw = (const float*)d_in[25];
    const float* fcb = (const float*)d_in[26];
    float* out = (float*)d_out;

    float *act0, *act1, *xw, *part, *scl, *shf;
    cudaGetSymbolAddress((void**)&act0, g_act0);
    cudaGetSymbolAddress((void**)&act1, g_act1);
    cudaGetSymbolAddress((void**)&xw,   g_xw);
    cudaGetSymbolAddress((void**)&part, g_part);
    cudaGetSymbolAddress((void**)&scl,  g_scale);
    cudaGetSymbolAddress((void**)&shf,  g_shift);

    // dynamic smem sizes for lstm kernels
    const int sm16  = (16  + 64 ) * 4;
    const int sm32  = (32  + 128) * 4;
    const int sm64  = (64  + 256) * 4;
    const int sm128 = (128 + 512 + 512 * 36) * 4;   // 76288 B
    cudaFuncSetAttribute(lstm_rec2<128, 96>,
                         cudaFuncAttributeMaxDynamicSharedMemorySize, sm128);

    // ---- layer 0: I=7, H=16 ----
    gemm_xw<7, 64, 64, true><<<dim3(1024, 1, 2), 256>>>(x, wih[0], bih[0], bhh[0],
                                                        nullptr, nullptr, xw);
    lstm_rec2<16, 16><<<dim3(64, 2), 64, sm16>>>(whh[0], xw, act0);
    bn_stats<32><<<256, 256>>>(act0, part);
    bn_finalize<<<1, 32>>>(part, gamma[0], beta[0], scl, shf, 32);

    // ---- layer 1: I=32, H=32 ----
    gemm_xw<32, 128, 128, false><<<dim3(1024, 1, 2), 256>>>(act0, wih[1], bih[1], bhh[1],
                                                            scl, shf, xw);
    lstm_rec2<32, 32><<<dim3(64, 2), 128, sm32>>>(whh[1], xw, act1);
    bn_stats<64><<<256, 256>>>(act1, part);
    bn_finalize<<<1, 64>>>(part, gamma[1], beta[1], scl, shf, 64);

    // ---- layer 2: I=64, H=64 ----
    gemm_xw<64, 256, 128, false><<<dim3(1024, 2, 2), 256>>>(act1, wih[2], bih[2], bhh[2],
                                                            scl, shf, xw);
    lstm_rec2<64, 64><<<dim3(64, 2), 256, sm64>>>(whh[2], xw, act0);
    bn_stats<128><<<256, 256>>>(act0, part);
    bn_finalize<<<1, 128>>>(part, gamma[2], beta[2], scl, shf, 128);

    // ---- layer 3: I=128, H=128 ----
    gemm_xw<128, 512, 128, false><<<dim3(1024, 4, 2), 256>>>(act0, wih[3], bih[3], bhh[3],
                                                             scl, shf, xw);
    lstm_rec2<128, 96><<<dim3(64, 2), 512, sm128>>>(whh[3], xw, act1);
    bn_stats<256><<<256, 256>>>(act1, part);
    bn_finalize<<<1, 256>>>(part, gamma[3], beta[3], scl, shf, 256);

    // ---- FC ----
    fc_kernel<<<8192, 256>>>(act1, scl, shf, fcw, fcb, out);
}